// round 2
// baseline (speedup 1.0000x reference)
#include <cuda_runtime.h>
#include <cuda_bf16.h>
#include <math.h>

// Problem constants
#define NN 100000      // nodes
#define EE 800000      // directed edges
#define E2 (EE + NN)   // edges + self loops
#define EF 16
#define HID 8
#define H1 8
#define C1 16
#define F1 (H1 * C1)   // 128
#define NC 16

// ---------------- scratch (device globals; no allocation allowed) -------------
// __align__(16) so float4 loads/atomics are legal.
__device__ __align__(16) float d_h0[NN * HID];        // NNConv accum -> h0
__device__ __align__(16) float d_cnt[NN];             // in-degree (float)
__device__ __align__(16) float d_hf1[NN * F1];        // GAT1 transformed features
__device__ __align__(16) float d_es1[NN * H1];
__device__ __align__(16) float d_ed1[NN * H1];
__device__ __align__(16) float d_z1[NN * H1];
__device__ __align__(16) float d_o1[NN * F1];         // GAT1 output accumulator
__device__ __align__(16) float d_hf2[NN * NC];        // GAT2 transformed features
__device__ __align__(16) float d_es2[NN];
__device__ __align__(16) float d_ed2[NN];
__device__ __align__(16) float d_z2[NN];

__device__ __forceinline__ float lrelu(float v) { return v > 0.f ? v : 0.2f * v; }

// ---------------- zero all accumulators ----------------
__global__ void zero_all(float* __restrict__ out) {
    int i = blockIdx.x * blockDim.x + threadIdx.x;
    if (i < NN * F1) d_o1[i] = 0.f;
    if (i < NN * HID) { d_h0[i] = 0.f; d_z1[i] = 0.f; }
    if (i < NN) { d_cnt[i] = 0.f; d_z2[i] = 0.f; }
    if (i < NN * NC) out[i] = 0.f;
}

// ---------------- NNConv edge pass: edge MLP + scatter ----------------
__global__ void nnconv_edge(const float* __restrict__ x,
                            const int* __restrict__ ei,
                            const float* __restrict__ ea,
                            const float* __restrict__ w1, const float* __restrict__ b1,
                            const float* __restrict__ w2, const float* __restrict__ b2) {
    __shared__ float sw1[EF * HID];
    __shared__ float sw2[HID * HID];
    __shared__ float sb1[HID];
    __shared__ float sb2[HID];
    int t = threadIdx.x;
    if (t < EF * HID) sw1[t] = w1[t];
    if (t < HID * HID) sw2[t] = w2[t];
    if (t < HID) { sb1[t] = b1[t]; sb2[t] = b2[t]; }
    __syncthreads();

    int e = blockIdx.x * blockDim.x + t;
    if (e >= EE) return;
    int s = ei[e];
    int d = ei[EE + e];

    float a[EF];
    const float4* ea4 = (const float4*)(ea) + e * 4;
#pragma unroll
    for (int j = 0; j < 4; j++) {
        float4 v = ea4[j];
        a[j * 4 + 0] = v.x; a[j * 4 + 1] = v.y; a[j * 4 + 2] = v.z; a[j * 4 + 3] = v.w;
    }

    float hm[HID];
#pragma unroll
    for (int k = 0; k < HID; k++) {
        float acc = sb1[k];
#pragma unroll
        for (int i = 0; i < EF; i++) acc = fmaf(a[i], sw1[i * HID + k], acc);
        hm[k] = fmaxf(acc, 0.f);
    }

    float xs = x[s];
    float we[HID];
#pragma unroll
    for (int o = 0; o < HID; o++) {
        float acc = sb2[o];
#pragma unroll
        for (int k = 0; k < HID; k++) acc = fmaf(hm[k], sw2[k * HID + o], acc);
        we[o] = xs * acc;
    }
    float4* dst4 = (float4*)(&d_h0[d * HID]);
    atomicAdd(dst4 + 0, make_float4(we[0], we[1], we[2], we[3]));
    atomicAdd(dst4 + 1, make_float4(we[4], we[5], we[6], we[7]));
    atomicAdd(&d_cnt[d], 1.0f);
}

// ---------------- NNConv node pass: mean + root + relu ----------------
__global__ void nnconv_node(const float* __restrict__ x,
                            const float* __restrict__ root,
                            const float* __restrict__ nnb) {
    int n = blockIdx.x * blockDim.x + threadIdx.x;
    if (n >= NN) return;
    float inv = 1.f / fmaxf(d_cnt[n], 1.f);
    float xr = x[n];
#pragma unroll
    for (int o = 0; o < HID; o++) {
        float v = d_h0[n * HID + o] * inv + xr * root[o] + nnb[o];
        d_h0[n * HID + o] = fmaxf(v, 0.f);
    }
}

// ---------------- GAT1 feature transform + attention logits ----------------
__global__ void gat1_feat(const float* __restrict__ g1W,
                          const float* __restrict__ g1as,
                          const float* __restrict__ g1ad) {
    __shared__ float sW[HID * F1];   // 4KB
    __shared__ float sas[F1];
    __shared__ float sad[F1];
    int t = threadIdx.x;
    for (int i = t; i < HID * F1; i += blockDim.x) sW[i] = g1W[i];
    if (t < F1) { sas[t] = g1as[t]; sad[t] = g1ad[t]; }
    __syncthreads();

    int n = blockIdx.x * blockDim.x + t;
    if (n >= NN) return;
    float h[HID];
#pragma unroll
    for (int k = 0; k < HID; k++) h[k] = d_h0[n * HID + k];

#pragma unroll
    for (int hh = 0; hh < H1; hh++) {
        float es = 0.f, ed = 0.f;
#pragma unroll
        for (int c = 0; c < C1; c++) {
            int j = hh * C1 + c;
            float acc = 0.f;
#pragma unroll
            for (int k = 0; k < HID; k++) acc = fmaf(h[k], sW[k * F1 + j], acc);
            d_hf1[n * F1 + j] = acc;
            es = fmaf(acc, sas[j], es);
            ed = fmaf(acc, sad[j], ed);
        }
        d_es1[n * H1 + hh] = es;
        d_ed1[n * H1 + hh] = ed;
    }
}

// ---------------- GAT1 softmax denominator ----------------
__global__ void gat1_z(const int* __restrict__ ei) {
    int e = blockIdx.x * blockDim.x + threadIdx.x;
    if (e >= E2) return;
    int s, d;
    if (e < EE) { s = ei[e]; d = ei[EE + e]; }
    else { s = e - EE; d = s; }
    float w[H1];
#pragma unroll
    for (int hh = 0; hh < H1; hh++)
        w[hh] = expf(lrelu(d_es1[s * H1 + hh] + d_ed1[d * H1 + hh]));
    float4* z4 = (float4*)(&d_z1[d * H1]);
    atomicAdd(z4 + 0, make_float4(w[0], w[1], w[2], w[3]));
    atomicAdd(z4 + 1, make_float4(w[4], w[5], w[6], w[7]));
}

// ---------------- GAT1 aggregate: warp per edge, float4 atomics ----------------
__global__ void gat1_aggr(const int* __restrict__ ei) {
    long long gtid = (long long)blockIdx.x * blockDim.x + threadIdx.x;
    int e = (int)(gtid >> 5);
    int lane = threadIdx.x & 31;
    if (e >= E2) return;
    int s, d;
    if (e < EE) { s = ei[e]; d = ei[EE + e]; }
    else { s = e - EE; d = s; }
    int hh = lane >> 2;   // 4 lanes (= 16 floats) per head
    float es = d_es1[s * H1 + hh];
    float ed = d_ed1[d * H1 + hh];
    float z  = d_z1[d * H1 + hh];
    float alpha = expf(lrelu(es + ed)) / (z + 1e-16f);
    float4 v = ((const float4*)d_hf1)[s * 32 + lane];
    float4 av = make_float4(v.x * alpha, v.y * alpha, v.z * alpha, v.w * alpha);
    atomicAdd(((float4*)d_o1) + d * 32 + lane, av);
}

// ---------------- GAT1 epilogue (bias+ELU) fused with GAT2 transform ----------------
__global__ void gat2_feat(const float* __restrict__ g1b,
                          const float* __restrict__ g2W,
                          const float* __restrict__ g2as,
                          const float* __restrict__ g2ad) {
    __shared__ float sW[F1 * NC];   // 8KB
    __shared__ float sb[F1];
    __shared__ float sas[NC];
    __shared__ float sad[NC];
    int t = threadIdx.x;
    for (int i = t; i < F1 * NC; i += blockDim.x) sW[i] = g2W[i];
    if (t < F1) sb[t] = g1b[t];
    if (t < NC) { sas[t] = g2as[t]; sad[t] = g2ad[t]; }
    __syncthreads();

    int n = blockIdx.x * blockDim.x + t;
    if (n >= NN) return;
    float acc[NC];
#pragma unroll
    for (int c = 0; c < NC; c++) acc[c] = 0.f;

#pragma unroll 4
    for (int j = 0; j < F1; j++) {
        float v = d_o1[n * F1 + j] + sb[j];
        v = v > 0.f ? v : (expf(v) - 1.f);   // ELU
#pragma unroll
        for (int c = 0; c < NC; c++) acc[c] = fmaf(v, sW[j * NC + c], acc[c]);
    }
    float es = 0.f, ed = 0.f;
#pragma unroll
    for (int c = 0; c < NC; c++) {
        d_hf2[n * NC + c] = acc[c];
        es = fmaf(acc[c], sas[c], es);
        ed = fmaf(acc[c], sad[c], ed);
    }
    d_es2[n] = es;
    d_ed2[n] = ed;
}

// ---------------- GAT2 softmax denominator ----------------
__global__ void gat2_z(const int* __restrict__ ei) {
    int e = blockIdx.x * blockDim.x + threadIdx.x;
    if (e >= E2) return;
    int s, d;
    if (e < EE) { s = ei[e]; d = ei[EE + e]; }
    else { s = e - EE; d = s; }
    float w = expf(lrelu(d_es2[s] + d_ed2[d]));
    atomicAdd(&d_z2[d], w);
}

// ---------------- GAT2 aggregate into d_out ----------------
__global__ void gat2_aggr(const int* __restrict__ ei, float* __restrict__ out) {
    int e = blockIdx.x * blockDim.x + threadIdx.x;
    if (e >= E2) return;
    int s, d;
    if (e < EE) { s = ei[e]; d = ei[EE + e]; }
    else { s = e - EE; d = s; }
    float alpha = expf(lrelu(d_es2[s] + d_ed2[d])) / (d_z2[d] + 1e-16f);
    const float4* src4 = (const float4*)(&d_hf2[s * NC]);
    float4* out4 = (float4*)(&out[d * NC]);
#pragma unroll
    for (int j = 0; j < 4; j++) {
        float4 v = src4[j];
        atomicAdd(out4 + j, make_float4(v.x * alpha, v.y * alpha, v.z * alpha, v.w * alpha));
    }
}

// ---------------- bias + log_softmax ----------------
__global__ void finish_logsoftmax(float* __restrict__ out, const float* __restrict__ g2b) {
    int n = blockIdx.x * blockDim.x + threadIdx.x;
    if (n >= NN) return;
    float v[NC];
    float m = -1e30f;
#pragma unroll
    for (int c = 0; c < NC; c++) {
        v[c] = out[n * NC + c] + g2b[c];
        m = fmaxf(m, v[c]);
    }
    float ssum = 0.f;
#pragma unroll
    for (int c = 0; c < NC; c++) ssum += expf(v[c] - m);
    float l = m + logf(ssum);
#pragma unroll
    for (int c = 0; c < NC; c++) out[n * NC + c] = v[c] - l;
}

extern "C" void kernel_launch(void* const* d_in, const int* in_sizes, int n_in,
                              void* d_out, int out_size) {
    const float* x    = (const float*)d_in[0];
    const int*   ei   = (const int*)d_in[1];     // int32: JAX x64 disabled
    const float* ea   = (const float*)d_in[2];
    const float* w1   = (const float*)d_in[3];
    const float* b1   = (const float*)d_in[4];
    const float* w2   = (const float*)d_in[5];
    const float* b2   = (const float*)d_in[6];
    const float* root = (const float*)d_in[7];
    const float* nnb  = (const float*)d_in[8];
    const float* g1W  = (const float*)d_in[9];
    const float* g1as = (const float*)d_in[10];
    const float* g1ad = (const float*)d_in[11];
    const float* g1b  = (const float*)d_in[12];
    const float* g2W  = (const float*)d_in[13];
    const float* g2as = (const float*)d_in[14];
    const float* g2ad = (const float*)d_in[15];
    const float* g2b  = (const float*)d_in[16];
    float* out = (float*)d_out;

    const int TB = 256;
    zero_all<<<(NN * F1 + TB - 1) / TB, TB>>>(out);
    nnconv_edge<<<(EE + TB - 1) / TB, TB>>>(x, ei, ea, w1, b1, w2, b2);
    nnconv_node<<<(NN + TB - 1) / TB, TB>>>(x, root, nnb);
    gat1_feat<<<(NN + TB - 1) / TB, TB>>>(g1W, g1as, g1ad);
    gat1_z<<<(E2 + TB - 1) / TB, TB>>>(ei);
    gat1_aggr<<<(int)(((long long)E2 * 32 + TB - 1) / TB), TB>>>(ei);
    gat2_feat<<<(NN + TB - 1) / TB, TB>>>(g1b, g2W, g2as, g2ad);
    gat2_z<<<(E2 + TB - 1) / TB, TB>>>(ei);
    gat2_aggr<<<(E2 + TB - 1) / TB, TB>>>(ei, out);
    finish_logsoftmax<<<(NN + TB - 1) / TB, TB>>>(out, g2b);
}